// round 7
// baseline (speedup 1.0000x reference)
#include <cuda_runtime.h>
#include <cuda_bf16.h>
#include <stdint.h>
#include <math.h>

#define N_TOT   8192
#define BHALF   4096
#define DD      128
#define T_TILES 32
// sqrt(2 * log2(e)): Gram entries come out as (sim/T)*log2(e) -> bare ex2
#define SC 1.698644f

// ---- scratch ---------------------------------------------------------------
__device__ __nv_bfloat16 g_Wb[N_TOT * DD];
__device__ float g_pos[N_TOT];
__device__ float g_rowsumP[2 * N_TOT];
__device__ unsigned g_ticket;      // zero-init; last CTA resets -> replay-safe

// ---- helpers ---------------------------------------------------------------
__device__ __forceinline__ uint32_t smem_u32(const void* p) {
    uint32_t a;
    asm("{ .reg .u64 t; cvta.to.shared.u64 t, %1; cvt.u32.u64 %0, t; }" : "=r"(a) : "l"(p));
    return a;
}
__device__ __forceinline__ float ex2f(float x) {
    float y; asm("ex2.approx.f32 %0, %1;" : "=f"(y) : "f"(x)); return y;
}
__device__ __forceinline__ void ldsm_x4(uint32_t* r, uint32_t addr) {
    asm volatile("ldmatrix.sync.aligned.m8n8.x4.shared.b16 {%0,%1,%2,%3}, [%4];"
                 : "=r"(r[0]), "=r"(r[1]), "=r"(r[2]), "=r"(r[3]) : "r"(addr));
}
__device__ __forceinline__ void mma16816(float* c, const uint32_t* a, uint32_t b0, uint32_t b1) {
    asm volatile("mma.sync.aligned.m16n8k16.row.col.f32.bf16.bf16.f32 "
                 "{%0,%1,%2,%3}, {%4,%5,%6,%7}, {%8,%9}, {%0,%1,%2,%3};"
                 : "+f"(c[0]), "+f"(c[1]), "+f"(c[2]), "+f"(c[3])
                 : "r"(a[0]), "r"(a[1]), "r"(a[2]), "r"(a[3]), "r"(b0), "r"(b1));
}
#define CP_COMMIT() asm volatile("cp.async.commit_group;" ::: "memory")
#define CP_WAIT0()  asm volatile("cp.async.wait_group 0;" ::: "memory")

__device__ __forceinline__ void cp_tile(uint32_t dstBase, int gRow, int tid) {
    const char* src = (const char*)g_Wb + (size_t)gRow * 256;
    #pragma unroll
    for (int i = 0; i < 8; ++i) {
        int idx = tid + i * 256;
        int row = idx >> 4, c = idx & 15;
        uint32_t d = dstBase + row * 256 + ((c ^ (row & 7)) << 4);
        const char* s = src + row * 256 + c * 16;
        asm volatile("cp.async.cg.shared.global [%0], [%1], 16;" :: "r"(d), "l"(s) : "memory");
    }
}

// ---------------------------------------------------------------------------
// Kernel 1: fused normalize (log2-domain scale) + positive-pair logits.
// One warp per pair (r, r+BHALF).
// ---------------------------------------------------------------------------
__global__ void __launch_bounds__(256) k_normpos(const float* __restrict__ zi,
                                                 const float* __restrict__ zj) {
    int warp = threadIdx.x >> 5, lane = threadIdx.x & 31;
    int r = blockIdx.x * 8 + warp;                 // 0..4095
    float4 a = reinterpret_cast<const float4*>(zi + (size_t)r * DD)[lane];
    float4 b = reinterpret_cast<const float4*>(zj + (size_t)r * DD)[lane];
    float aa = a.x * a.x + a.y * a.y + a.z * a.z + a.w * a.w;
    float bb = b.x * b.x + b.y * b.y + b.z * b.z + b.w * b.w;
    float ab = a.x * b.x + a.y * b.y + a.z * b.z + a.w * b.w;
    #pragma unroll
    for (int o = 16; o; o >>= 1) {
        aa += __shfl_xor_sync(0xFFFFFFFFu, aa, o);
        bb += __shfl_xor_sync(0xFFFFFFFFu, bb, o);
        ab += __shfl_xor_sync(0xFFFFFFFFu, ab, o);
    }
    float na = fmaxf(sqrtf(aa), 1e-8f), nb = fmaxf(sqrtf(bb), 1e-8f);
    float sa = SC / na, sb2 = SC / nb;
    __nv_bfloat162 p0 = __floats2bfloat162_rn(a.x * sa, a.y * sa);
    __nv_bfloat162 p1 = __floats2bfloat162_rn(a.z * sa, a.w * sa);
    uint2 oa; oa.x = *(uint32_t*)&p0; oa.y = *(uint32_t*)&p1;
    reinterpret_cast<uint2*>(g_Wb + (size_t)r * DD)[lane] = oa;
    __nv_bfloat162 q0 = __floats2bfloat162_rn(b.x * sb2, b.y * sb2);
    __nv_bfloat162 q1 = __floats2bfloat162_rn(b.z * sb2, b.w * sb2);
    uint2 ob; ob.x = *(uint32_t*)&q0; ob.y = *(uint32_t*)&q1;
    reinterpret_cast<uint2*>(g_Wb + (size_t)(r + BHALF) * DD)[lane] = ob;
    if (lane == 0) {
        float p = 2.0f * ab / (na * nb);
        g_pos[r] = p;
        g_pos[r + BHALF] = p;
    }
}

// ---------------------------------------------------------------------------
// GEMM building blocks
// ---------------------------------------------------------------------------
__device__ __forceinline__ void mma_tile(uint32_t sA, uint32_t cb,
                                         int aRowG, int aK, int bJG, int bK,
                                         float (&c)[4][4][4]) {
    #pragma unroll
    for (int ks = 0; ks < 8; ++ks) {
        uint32_t a[4][4], b[2][4];
        #pragma unroll
        for (int mi = 0; mi < 4; ++mi) {
            int r = aRowG + mi * 16;
            int k = ks * 16 + aK;
            ldsm_x4(a[mi], sA + r * 256 + (((k >> 3) ^ (r & 7)) << 4));
        }
        #pragma unroll
        for (int nj = 0; nj < 2; ++nj) {
            int j = bJG + nj * 16;
            int k = ks * 16 + bK;
            ldsm_x4(b[nj], cb + j * 256 + (((k >> 3) ^ (j & 7)) << 4));
        }
        #pragma unroll
        for (int mi = 0; mi < 4; ++mi) {
            mma16816(c[mi][0], a[mi], b[0][0], b[0][1]);
            mma16816(c[mi][1], a[mi], b[0][2], b[0][3]);
            mma16816(c[mi][2], a[mi], b[1][0], b[1][1]);
            mma16816(c[mi][3], a[mi], b[1][2], b[1][3]);
        }
    }
}

// epilogue of tile t: exp2, (diag tile only: mask), accumulate row sums, zero c
__device__ __forceinline__ void epi_tile(float (&c)[4][4][4], float (&rAcc)[8],
                                         bool diag, int t, int h,
                                         int warpM, int warpN, int lane, int rowBase) {
    if (!diag) {
        #pragma unroll
        for (int mi = 0; mi < 4; ++mi) {
            float s0 = 0.f, s1 = 0.f;
            #pragma unroll
            for (int nf = 0; nf < 4; ++nf) {
                s0 += ex2f(c[mi][nf][0]); s0 += ex2f(c[mi][nf][1]);
                s1 += ex2f(c[mi][nf][2]); s1 += ex2f(c[mi][nf][3]);
            }
            rAcc[mi * 2]     += s0;
            rAcc[mi * 2 + 1] += s1;
        }
    } else {
        int colT = h * 4096 + t * 128 + warpN * 32 + (lane & 3) * 2;
        int rT = rowBase + warpM * 64 + (lane >> 2);
        #pragma unroll
        for (int mi = 0; mi < 4; ++mi) {
            int r0 = rT + mi * 16, r1 = r0 + 8;
            float s0 = 0.f, s1 = 0.f;
            #pragma unroll
            for (int nf = 0; nf < 4; ++nf) {
                int c0 = colT + nf * 8;
                float e0 = ex2f(c[mi][nf][0]);
                float e1 = ex2f(c[mi][nf][1]);
                float e2 = ex2f(c[mi][nf][2]);
                float e3 = ex2f(c[mi][nf][3]);
                s0 += (c0 != r0)     ? e0 : 0.f;
                s0 += (c0 + 1 != r0) ? e1 : 0.f;
                s1 += (c0 != r1)     ? e2 : 0.f;
                s1 += (c0 + 1 != r1) ? e3 : 0.f;
            }
            rAcc[mi * 2]     += s0;
            rAcc[mi * 2 + 1] += s1;
        }
    }
    #pragma unroll
    for (int mi = 0; mi < 4; ++mi)
        #pragma unroll
        for (int nf = 0; nf < 4; ++nf)
            #pragma unroll
            for (int q = 0; q < 4; ++q) c[mi][nf][q] = 0.0f;
}

// ---------------------------------------------------------------------------
// Kernel 2: HMMA Gram + fused exp/row-sum + in-kernel final reduction.
// Grid (2, 64). Pipelined: MMA(t) overlaps epilogue(t-1) via c0/c1.
// ---------------------------------------------------------------------------
extern __shared__ char smem_g[];

__global__ void __launch_bounds__(256, 1) k_gemm(float* __restrict__ out) {
    uint32_t sA = smem_u32(smem_g);
    uint32_t sB0 = sA + 32768, sB1 = sA + 65536;

    int tid = threadIdx.x, lane = tid & 31, wid = tid >> 5;
    int warpM = wid >> 2, warpN = wid & 3;
    int h = blockIdx.x;
    int by = blockIdx.y;
    int rowBase = by * 128;
    int st = by - 32 * h;                      // diagonal tile index (may be <0 / >=32)

    int aRow = lane & 15;
    int aK   = (lane >> 4) << 3;
    int bJ   = (lane & 7) + ((lane >> 4) << 3);
    int bK   = ((lane >> 3) & 1) << 3;
    int aRowG = warpM * 64 + aRow;
    int bJG   = warpN * 32 + bJ;

    // prologue: A + B0
    cp_tile(sA, rowBase, tid);
    cp_tile(sB0, h * 4096, tid);
    CP_COMMIT();
    CP_WAIT0();
    __syncthreads();

    float c0[4][4][4], c1[4][4][4], rAcc[8];
    #pragma unroll
    for (int i = 0; i < 8; ++i) rAcc[i] = 0.f;
    #pragma unroll
    for (int mi = 0; mi < 4; ++mi)
        #pragma unroll
        for (int nf = 0; nf < 4; ++nf)
            #pragma unroll
            for (int q = 0; q < 4; ++q) { c0[mi][nf][q] = 0.f; c1[mi][nf][q] = 0.f; }

    // t = 0 (even -> c0, buffer sB0); prefetch tile 1 -> sB1
    cp_tile(sB1, h * 4096 + 128, tid);
    CP_COMMIT();
    mma_tile(sA, sB0, aRowG, aK, bJG, bK, c0);
    CP_WAIT0();
    __syncthreads();

    for (int tt = 1; tt < 31; tt += 2) {
        // t = tt (odd -> c1, sB1); prefetch tt+1 -> sB0
        cp_tile(sB0, h * 4096 + (tt + 1) * 128, tid);
        CP_COMMIT();
        mma_tile(sA, sB1, aRowG, aK, bJG, bK, c1);
        epi_tile(c0, rAcc, (tt - 1) == st, tt - 1, h, warpM, warpN, lane, rowBase);
        CP_WAIT0();
        __syncthreads();

        // t = tt+1 (even -> c0, sB0); prefetch tt+2 -> sB1
        if (tt + 2 < T_TILES) {
            cp_tile(sB1, h * 4096 + (tt + 2) * 128, tid);
            CP_COMMIT();
        }
        mma_tile(sA, sB0, aRowG, aK, bJG, bK, c0);
        epi_tile(c1, rAcc, tt == st, tt, h, warpM, warpN, lane, rowBase);
        CP_WAIT0();
        __syncthreads();
    }

    // t = 31 (odd -> c1, sB1)
    mma_tile(sA, sB1, aRowG, aK, bJG, bK, c1);
    epi_tile(c0, rAcc, 30 == st, 30, h, warpM, warpN, lane, rowBase);
    epi_tile(c1, rAcc, 31 == st, 31, h, warpM, warpN, lane, rowBase);
    __syncthreads();                       // all ldsm done; smem reusable

    // cross-warp row reduction
    float* sRed = (float*)smem_g;          // [128][17]
    #pragma unroll
    for (int mi = 0; mi < 4; ++mi)
        #pragma unroll
        for (int hf = 0; hf < 2; ++hf) {
            int r = warpM * 64 + mi * 16 + (lane >> 2) + hf * 8;
            sRed[r * 17 + warpN * 4 + (lane & 3)] = rAcc[mi * 2 + hf];
        }
    __syncthreads();
    if (tid < 128) {
        float s = 0.0f;
        #pragma unroll
        for (int j = 0; j < 16; ++j) s += sRed[tid * 17 + j];
        g_rowsumP[h * N_TOT + rowBase + tid] = s;
    }
    __syncthreads();

    // last-CTA final reduction (deterministic order)
    volatile unsigned* flag = (volatile unsigned*)(smem_g + 12288);
    if (tid == 0) {
        __threadfence();
        unsigned v = atomicAdd(&g_ticket, 1u);
        *flag = (v == 127u) ? 1u : 0u;
    }
    __syncthreads();
    if (*flag) {
        float acc = 0.0f;
        for (int i = tid; i < N_TOT; i += 256) {
            float s = __ldcg(&g_rowsumP[i]) + __ldcg(&g_rowsumP[N_TOT + i]);
            acc += __logf(s) - g_pos[i];
        }
        #pragma unroll
        for (int o = 16; o; o >>= 1) acc += __shfl_xor_sync(0xFFFFFFFFu, acc, o);
        float* wsum = (float*)(smem_g + 12352);
        if (lane == 0) wsum[wid] = acc;
        __syncthreads();
        if (tid == 0) {
            float tot = 0.f;
            #pragma unroll
            for (int w = 0; w < 8; ++w) tot += wsum[w];
            out[0] = tot * (1.0f / (float)N_TOT);
            g_ticket = 0u;                 // reset for graph replay
        }
    }
}

// ---------------------------------------------------------------------------
extern "C" void kernel_launch(void* const* d_in, const int* in_sizes, int n_in,
                              void* d_out, int out_size) {
    const float* zi = (const float*)d_in[0];
    const float* zj = (const float*)d_in[1];
    float* out = (float*)d_out;

    cudaFuncSetAttribute(k_gemm, cudaFuncAttributeMaxDynamicSharedMemorySize, 98304);

    k_normpos<<<BHALF / 8, 256>>>(zi, zj);
    k_gemm<<<dim3(2, 64), 256, 98304>>>(out);
}

// round 8
// speedup vs baseline: 1.0320x; 1.0320x over previous
#include <cuda_runtime.h>
#include <cuda_bf16.h>
#include <stdint.h>
#include <math.h>

#define N_TOT   8192
#define BHALF   4096
#define DD      128
#define T_TILES 16                 // 16 x 128 cols = 2048 cols per CTA
#define NSLICE  4
// sqrt(2 * log2(e)): Gram entries come out as (sim/T)*log2(e) -> bare ex2
#define SC 1.698644f

// ---- scratch ---------------------------------------------------------------
__device__ __nv_bfloat16 g_Wb[N_TOT * DD];
__device__ float g_pos[N_TOT];
__device__ float g_rowsumP[NSLICE * N_TOT];
__device__ unsigned g_ticket;      // zero-init; last CTA resets -> replay-safe

// ---- helpers ---------------------------------------------------------------
__device__ __forceinline__ uint32_t smem_u32(const void* p) {
    uint32_t a;
    asm("{ .reg .u64 t; cvta.to.shared.u64 t, %1; cvt.u32.u64 %0, t; }" : "=r"(a) : "l"(p));
    return a;
}
__device__ __forceinline__ float ex2f(float x) {
    float y; asm("ex2.approx.f32 %0, %1;" : "=f"(y) : "f"(x)); return y;
}
__device__ __forceinline__ void ldsm_x4(uint32_t* r, uint32_t addr) {
    asm volatile("ldmatrix.sync.aligned.m8n8.x4.shared.b16 {%0,%1,%2,%3}, [%4];"
                 : "=r"(r[0]), "=r"(r[1]), "=r"(r[2]), "=r"(r[3]) : "r"(addr));
}
__device__ __forceinline__ void mma16816(float* c, const uint32_t* a, uint32_t b0, uint32_t b1) {
    asm volatile("mma.sync.aligned.m16n8k16.row.col.f32.bf16.bf16.f32 "
                 "{%0,%1,%2,%3}, {%4,%5,%6,%7}, {%8,%9}, {%0,%1,%2,%3};"
                 : "+f"(c[0]), "+f"(c[1]), "+f"(c[2]), "+f"(c[3])
                 : "r"(a[0]), "r"(a[1]), "r"(a[2]), "r"(a[3]), "r"(b0), "r"(b1));
}
#define CP_COMMIT() asm volatile("cp.async.commit_group;" ::: "memory")
#define CP_WAIT0()  asm volatile("cp.async.wait_group 0;" ::: "memory")

__device__ __forceinline__ void cp_tile(uint32_t dstBase, int gRow, int tid) {
    const char* src = (const char*)g_Wb + (size_t)gRow * 256;
    #pragma unroll
    for (int i = 0; i < 8; ++i) {
        int idx = tid + i * 256;
        int row = idx >> 4, c = idx & 15;
        uint32_t d = dstBase + row * 256 + ((c ^ (row & 7)) << 4);
        const char* s = src + row * 256 + c * 16;
        asm volatile("cp.async.cg.shared.global [%0], [%1], 16;" :: "r"(d), "l"(s) : "memory");
    }
}

// ---------------------------------------------------------------------------
// Kernel 1: fused normalize (log2-domain scale) + positive-pair logits.
// ---------------------------------------------------------------------------
__global__ void __launch_bounds__(256) k_normpos(const float* __restrict__ zi,
                                                 const float* __restrict__ zj) {
    int warp = threadIdx.x >> 5, lane = threadIdx.x & 31;
    int r = blockIdx.x * 8 + warp;                 // 0..4095
    float4 a = reinterpret_cast<const float4*>(zi + (size_t)r * DD)[lane];
    float4 b = reinterpret_cast<const float4*>(zj + (size_t)r * DD)[lane];
    float aa = a.x * a.x + a.y * a.y + a.z * a.z + a.w * a.w;
    float bb = b.x * b.x + b.y * b.y + b.z * b.z + b.w * b.w;
    float ab = a.x * b.x + a.y * b.y + a.z * b.z + a.w * b.w;
    #pragma unroll
    for (int o = 16; o; o >>= 1) {
        aa += __shfl_xor_sync(0xFFFFFFFFu, aa, o);
        bb += __shfl_xor_sync(0xFFFFFFFFu, bb, o);
        ab += __shfl_xor_sync(0xFFFFFFFFu, ab, o);
    }
    float na = fmaxf(sqrtf(aa), 1e-8f), nb = fmaxf(sqrtf(bb), 1e-8f);
    float sa = SC / na, sb2 = SC / nb;
    __nv_bfloat162 p0 = __floats2bfloat162_rn(a.x * sa, a.y * sa);
    __nv_bfloat162 p1 = __floats2bfloat162_rn(a.z * sa, a.w * sa);
    uint2 oa; oa.x = *(uint32_t*)&p0; oa.y = *(uint32_t*)&p1;
    reinterpret_cast<uint2*>(g_Wb + (size_t)r * DD)[lane] = oa;
    __nv_bfloat162 q0 = __floats2bfloat162_rn(b.x * sb2, b.y * sb2);
    __nv_bfloat162 q1 = __floats2bfloat162_rn(b.z * sb2, b.w * sb2);
    uint2 ob; ob.x = *(uint32_t*)&q0; ob.y = *(uint32_t*)&q1;
    reinterpret_cast<uint2*>(g_Wb + (size_t)(r + BHALF) * DD)[lane] = ob;
    if (lane == 0) {
        float p = 2.0f * ab / (na * nb);
        g_pos[r] = p;
        g_pos[r + BHALF] = p;
    }
}

// ---------------------------------------------------------------------------
// GEMM building blocks
// ---------------------------------------------------------------------------
__device__ __forceinline__ void mma_tile(uint32_t sA, uint32_t cb,
                                         int aRowG, int aK, int bJG, int bK,
                                         float (&c)[4][4][4]) {
    #pragma unroll
    for (int ks = 0; ks < 8; ++ks) {
        uint32_t a[4][4], b[2][4];
        #pragma unroll
        for (int mi = 0; mi < 4; ++mi) {
            int r = aRowG + mi * 16;
            int k = ks * 16 + aK;
            ldsm_x4(a[mi], sA + r * 256 + (((k >> 3) ^ (r & 7)) << 4));
        }
        #pragma unroll
        for (int nj = 0; nj < 2; ++nj) {
            int j = bJG + nj * 16;
            int k = ks * 16 + bK;
            ldsm_x4(b[nj], cb + j * 256 + (((k >> 3) ^ (j & 7)) << 4));
        }
        #pragma unroll
        for (int mi = 0; mi < 4; ++mi) {
            mma16816(c[mi][0], a[mi], b[0][0], b[0][1]);
            mma16816(c[mi][1], a[mi], b[0][2], b[0][3]);
            mma16816(c[mi][2], a[mi], b[1][0], b[1][1]);
            mma16816(c[mi][3], a[mi], b[1][2], b[1][3]);
        }
    }
}

// epilogue of tile t: exp2, (diag tile only: mask), accumulate row sums, zero c
__device__ __forceinline__ void epi_tile(float (&c)[4][4][4], float (&rAcc)[8],
                                         bool diag, int colBase,
                                         int warpM, int warpN, int lane, int rowBase) {
    if (!diag) {
        #pragma unroll
        for (int mi = 0; mi < 4; ++mi) {
            float s0 = 0.f, s1 = 0.f;
            #pragma unroll
            for (int nf = 0; nf < 4; ++nf) {
                s0 += ex2f(c[mi][nf][0]); s0 += ex2f(c[mi][nf][1]);
                s1 += ex2f(c[mi][nf][2]); s1 += ex2f(c[mi][nf][3]);
            }
            rAcc[mi * 2]     += s0;
            rAcc[mi * 2 + 1] += s1;
        }
    } else {
        int colT = colBase + warpN * 32 + (lane & 3) * 2;
        int rT = rowBase + warpM * 64 + (lane >> 2);
        #pragma unroll
        for (int mi = 0; mi < 4; ++mi) {
            int r0 = rT + mi * 16, r1 = r0 + 8;
            float s0 = 0.f, s1 = 0.f;
            #pragma unroll
            for (int nf = 0; nf < 4; ++nf) {
                int c0 = colT + nf * 8;
                float e0 = ex2f(c[mi][nf][0]);
                float e1 = ex2f(c[mi][nf][1]);
                float e2 = ex2f(c[mi][nf][2]);
                float e3 = ex2f(c[mi][nf][3]);
                s0 += (c0 != r0)     ? e0 : 0.f;
                s0 += (c0 + 1 != r0) ? e1 : 0.f;
                s1 += (c0 != r1)     ? e2 : 0.f;
                s1 += (c0 + 1 != r1) ? e3 : 0.f;
            }
            rAcc[mi * 2]     += s0;
            rAcc[mi * 2 + 1] += s1;
        }
    }
    #pragma unroll
    for (int mi = 0; mi < 4; ++mi)
        #pragma unroll
        for (int nf = 0; nf < 4; ++nf)
            #pragma unroll
            for (int q = 0; q < 4; ++q) c[mi][nf][q] = 0.0f;
}

// ---------------------------------------------------------------------------
// Kernel 2: HMMA Gram + fused exp/row-sum + in-kernel final reduction.
// Grid (4, 64) = 256 CTAs, 2 CTA/SM. CTA = 128 rows x 2048 cols (16 tiles).
// ---------------------------------------------------------------------------
extern __shared__ char smem_g[];

__global__ void __launch_bounds__(256, 2) k_gemm(float* __restrict__ out) {
    uint32_t sA = smem_u32(smem_g);
    uint32_t sB0 = sA + 32768, sB1 = sA + 65536;

    int tid = threadIdx.x, lane = tid & 31, wid = tid >> 5;
    int warpM = wid >> 2, warpN = wid & 3;
    int bx = blockIdx.x;                       // column slice 0..3 (2048 cols each)
    int by = blockIdx.y;
    int rowBase = by * 128;
    int colBase0 = bx * 2048;
    int st = by - bx * 16;                     // diagonal tile index within this slice

    int aRow = lane & 15;
    int aK   = (lane >> 4) << 3;
    int bJ   = (lane & 7) + ((lane >> 4) << 3);
    int bK   = ((lane >> 3) & 1) << 3;
    int aRowG = warpM * 64 + aRow;
    int bJG   = warpN * 32 + bJ;

    // prologue: A + B0
    cp_tile(sA, rowBase, tid);
    cp_tile(sB0, colBase0, tid);
    CP_COMMIT();
    CP_WAIT0();
    __syncthreads();

    float c[4][4][4], rAcc[8];
    #pragma unroll
    for (int i = 0; i < 8; ++i) rAcc[i] = 0.f;
    #pragma unroll
    for (int mi = 0; mi < 4; ++mi)
        #pragma unroll
        for (int nf = 0; nf < 4; ++nf)
            #pragma unroll
            for (int q = 0; q < 4; ++q) c[mi][nf][q] = 0.f;

    for (int t = 0; t < T_TILES; ++t) {
        uint32_t cb = (t & 1) ? sB1 : sB0;
        if (t + 1 < T_TILES) {
            cp_tile((t & 1) ? sB0 : sB1, colBase0 + (t + 1) * 128, tid);
            CP_COMMIT();
        }
        mma_tile(sA, cb, aRowG, aK, bJG, bK, c);
        epi_tile(c, rAcc, t == st, colBase0 + t * 128, warpM, warpN, lane, rowBase);
        if (t + 1 < T_TILES) CP_WAIT0();
        __syncthreads();
    }

    // cross-warp row reduction
    float* sRed = (float*)smem_g;              // [128][17]
    #pragma unroll
    for (int mi = 0; mi < 4; ++mi)
        #pragma unroll
        for (int hf = 0; hf < 2; ++hf) {
            int r = warpM * 64 + mi * 16 + (lane >> 2) + hf * 8;
            sRed[r * 17 + warpN * 4 + (lane & 3)] = rAcc[mi * 2 + hf];
        }
    __syncthreads();
    if (tid < 128) {
        float s = 0.0f;
        #pragma unroll
        for (int j = 0; j < 16; ++j) s += sRed[tid * 17 + j];
        g_rowsumP[bx * N_TOT + rowBase + tid] = s;
    }
    __syncthreads();

    // last-CTA final reduction (deterministic order)
    volatile unsigned* flag = (volatile unsigned*)(smem_g + 12288);
    if (tid == 0) {
        __threadfence();
        unsigned v = atomicAdd(&g_ticket, 1u);
        *flag = (v == 255u) ? 1u : 0u;
    }
    __syncthreads();
    if (*flag) {
        float acc = 0.0f;
        for (int i = tid; i < N_TOT; i += 256) {
            float s = __ldcg(&g_rowsumP[i])          + __ldcg(&g_rowsumP[N_TOT + i]) +
                      __ldcg(&g_rowsumP[2 * N_TOT + i]) + __ldcg(&g_rowsumP[3 * N_TOT + i]);
            acc += __logf(s) - g_pos[i];
        }
        #pragma unroll
        for (int o = 16; o; o >>= 1) acc += __shfl_xor_sync(0xFFFFFFFFu, acc, o);
        float* wsum = (float*)(smem_g + 12352);
        if (lane == 0) wsum[wid] = acc;
        __syncthreads();
        if (tid == 0) {
            float tot = 0.f;
            #pragma unroll
            for (int w = 0; w < 8; ++w) tot += wsum[w];
            out[0] = tot * (1.0f / (float)N_TOT);
            g_ticket = 0u;                     // reset for graph replay
        }
    }
}

// ---------------------------------------------------------------------------
extern "C" void kernel_launch(void* const* d_in, const int* in_sizes, int n_in,
                              void* d_out, int out_size) {
    const float* zi = (const float*)d_in[0];
    const float* zj = (const float*)d_in[1];
    float* out = (float*)d_out;

    cudaFuncSetAttribute(k_gemm, cudaFuncAttributeMaxDynamicSharedMemorySize, 98304);

    k_normpos<<<BHALF / 8, 256>>>(zi, zj);
    k_gemm<<<dim3(NSLICE, 64), 256, 98304>>>(out);
}

// round 9
// speedup vs baseline: 1.6918x; 1.6393x over previous
#include <cuda_runtime.h>
#include <cuda_bf16.h>
#include <stdint.h>
#include <math.h>

#define N_TOT   8192
#define BHALF   4096
#define DD      128
#define NTILE   64                  // 64 x 64 tile grid, tiles 128x128
#define NPAIR   2080                // NTILE*(NTILE+1)/2 upper-triangle pairs
// sqrt(2 * log2(e)): Gram entries come out as (sim/T)*log2(e) -> bare ex2
#define SC 1.698644f

// ---- scratch ---------------------------------------------------------------
__device__ __nv_bfloat16 g_Wb[N_TOT * DD];
__device__ float g_pos[N_TOT];
__device__ float g_rowsum[N_TOT];       // atomically accumulated exp row sums
__device__ unsigned g_ticket;           // zero-init; last CTA resets -> replay-safe

// ---- helpers ---------------------------------------------------------------
__device__ __forceinline__ uint32_t smem_u32(const void* p) {
    uint32_t a;
    asm("{ .reg .u64 t; cvta.to.shared.u64 t, %1; cvt.u32.u64 %0, t; }" : "=r"(a) : "l"(p));
    return a;
}
__device__ __forceinline__ float ex2f(float x) {
    float y; asm("ex2.approx.f32 %0, %1;" : "=f"(y) : "f"(x)); return y;
}
__device__ __forceinline__ void ldsm_x4(uint32_t* r, uint32_t addr) {
    asm volatile("ldmatrix.sync.aligned.m8n8.x4.shared.b16 {%0,%1,%2,%3}, [%4];"
                 : "=r"(r[0]), "=r"(r[1]), "=r"(r[2]), "=r"(r[3]) : "r"(addr));
}
__device__ __forceinline__ void mma16816(float* c, const uint32_t* a, uint32_t b0, uint32_t b1) {
    asm volatile("mma.sync.aligned.m16n8k16.row.col.f32.bf16.bf16.f32 "
                 "{%0,%1,%2,%3}, {%4,%5,%6,%7}, {%8,%9}, {%0,%1,%2,%3};"
                 : "+f"(c[0]), "+f"(c[1]), "+f"(c[2]), "+f"(c[3])
                 : "r"(a[0]), "r"(a[1]), "r"(a[2]), "r"(a[3]), "r"(b0), "r"(b1));
}
#define CP_COMMIT() asm volatile("cp.async.commit_group;" ::: "memory")
#define CP_WAIT0()  asm volatile("cp.async.wait_group 0;" ::: "memory")

__device__ __forceinline__ void cp_tile(uint32_t dstBase, int gRow, int tid) {
    const char* src = (const char*)g_Wb + (size_t)gRow * 256;
    #pragma unroll
    for (int i = 0; i < 8; ++i) {
        int idx = tid + i * 256;
        int row = idx >> 4, c = idx & 15;
        uint32_t d = dstBase + row * 256 + ((c ^ (row & 7)) << 4);
        const char* s = src + row * 256 + c * 16;
        asm volatile("cp.async.cg.shared.global [%0], [%1], 16;" :: "r"(d), "l"(s) : "memory");
    }
}

// cumulative pair count before tile-row I
__device__ __forceinline__ int cumC(int I) { return NTILE * I - (I * (I - 1)) / 2; }

// ---------------------------------------------------------------------------
// Kernel 1: fused normalize (log2-domain scale) + positive pairs + zero rowsum.
// ---------------------------------------------------------------------------
__global__ void __launch_bounds__(256) k_normpos(const float* __restrict__ zi,
                                                 const float* __restrict__ zj) {
    int gtid = blockIdx.x * 256 + threadIdx.x;
    if (gtid < N_TOT) g_rowsum[gtid] = 0.0f;

    int warp = threadIdx.x >> 5, lane = threadIdx.x & 31;
    int r = blockIdx.x * 8 + warp;                 // 0..4095
    float4 a = reinterpret_cast<const float4*>(zi + (size_t)r * DD)[lane];
    float4 b = reinterpret_cast<const float4*>(zj + (size_t)r * DD)[lane];
    float aa = a.x * a.x + a.y * a.y + a.z * a.z + a.w * a.w;
    float bb = b.x * b.x + b.y * b.y + b.z * b.z + b.w * b.w;
    float ab = a.x * b.x + a.y * b.y + a.z * b.z + a.w * b.w;
    #pragma unroll
    for (int o = 16; o; o >>= 1) {
        aa += __shfl_xor_sync(0xFFFFFFFFu, aa, o);
        bb += __shfl_xor_sync(0xFFFFFFFFu, bb, o);
        ab += __shfl_xor_sync(0xFFFFFFFFu, ab, o);
    }
    float na = fmaxf(sqrtf(aa), 1e-8f), nb = fmaxf(sqrtf(bb), 1e-8f);
    float sa = SC / na, sb2 = SC / nb;
    __nv_bfloat162 p0 = __floats2bfloat162_rn(a.x * sa, a.y * sa);
    __nv_bfloat162 p1 = __floats2bfloat162_rn(a.z * sa, a.w * sa);
    uint2 oa; oa.x = *(uint32_t*)&p0; oa.y = *(uint32_t*)&p1;
    reinterpret_cast<uint2*>(g_Wb + (size_t)r * DD)[lane] = oa;
    __nv_bfloat162 q0 = __floats2bfloat162_rn(b.x * sb2, b.y * sb2);
    __nv_bfloat162 q1 = __floats2bfloat162_rn(b.z * sb2, b.w * sb2);
    uint2 ob; ob.x = *(uint32_t*)&q0; ob.y = *(uint32_t*)&q1;
    reinterpret_cast<uint2*>(g_Wb + (size_t)(r + BHALF) * DD)[lane] = ob;
    if (lane == 0) {
        float p = 2.0f * ab / (na * nb);
        g_pos[r] = p;
        g_pos[r + BHALF] = p;
    }
}

// ---------------------------------------------------------------------------
// Kernel 2: symmetric HMMA Gram. One 128x128 tile pair (I<=J) per CTA.
// Row sums -> block I, column sums -> block J (symmetry). Diag tiles masked.
// ---------------------------------------------------------------------------
extern __shared__ char smem_g[];

__global__ void __launch_bounds__(256, 2) k_gemm(float* __restrict__ out) {
    uint32_t sA = smem_u32(smem_g);
    uint32_t sB = sA + 32768;

    int tid = threadIdx.x, lane = tid & 31, wid = tid >> 5;
    int warpM = wid >> 2, warpN = wid & 3;

    // map linear pair id -> (I, J), I <= J
    int p = blockIdx.x;
    int I = (int)(64.5f - sqrtf(fmaxf(64.5f * 64.5f - 2.0f * (float)p, 0.0f)));
    while (cumC(I + 1) <= p) ++I;
    while (cumC(I) > p) --I;
    int J = I + (p - cumC(I));
    bool diag = (I == J);
    int rowBase = I * 128, colBase = J * 128;

    // loads
    cp_tile(sA, rowBase, tid);
    cp_tile(sB, colBase, tid);
    CP_COMMIT();
    CP_WAIT0();
    __syncthreads();

    // fragment lane patterns
    int aRow = lane & 15;
    int aK   = (lane >> 4) << 3;
    int bJ   = (lane & 7) + ((lane >> 4) << 3);
    int bK   = ((lane >> 3) & 1) << 3;
    int aRowG = warpM * 64 + aRow;
    int bJG   = warpN * 32 + bJ;

    float c[4][4][4];
    #pragma unroll
    for (int mi = 0; mi < 4; ++mi)
        #pragma unroll
        for (int nf = 0; nf < 4; ++nf)
            #pragma unroll
            for (int q = 0; q < 4; ++q) c[mi][nf][q] = 0.f;

    #pragma unroll
    for (int ks = 0; ks < 8; ++ks) {
        uint32_t a[4][4], b[2][4];
        #pragma unroll
        for (int mi = 0; mi < 4; ++mi) {
            int r = aRowG + mi * 16;
            int k = ks * 16 + aK;
            ldsm_x4(a[mi], sA + r * 256 + (((k >> 3) ^ (r & 7)) << 4));
        }
        #pragma unroll
        for (int nj = 0; nj < 2; ++nj) {
            int j = bJG + nj * 16;
            int k = ks * 16 + bK;
            ldsm_x4(b[nj], sB + j * 256 + (((k >> 3) ^ (j & 7)) << 4));
        }
        #pragma unroll
        for (int mi = 0; mi < 4; ++mi) {
            mma16816(c[mi][0], a[mi], b[0][0], b[0][1]);
            mma16816(c[mi][1], a[mi], b[0][2], b[0][3]);
            mma16816(c[mi][2], a[mi], b[1][0], b[1][1]);
            mma16816(c[mi][3], a[mi], b[1][2], b[1][3]);
        }
    }
    __syncthreads();                     // all ldsm done -> smem reusable

    // exp2 in place; mask diagonal by zeroing (removes the self term)
    #pragma unroll
    for (int mi = 0; mi < 4; ++mi)
        #pragma unroll
        for (int nf = 0; nf < 4; ++nf)
            #pragma unroll
            for (int q = 0; q < 4; ++q) c[mi][nf][q] = ex2f(c[mi][nf][q]);

    if (diag) {
        int colT = colBase + warpN * 32 + (lane & 3) * 2;
        int rT = rowBase + warpM * 64 + (lane >> 2);
        #pragma unroll
        for (int mi = 0; mi < 4; ++mi) {
            int r0 = rT + mi * 16, r1 = r0 + 8;
            #pragma unroll
            for (int nf = 0; nf < 4; ++nf) {
                int c0 = colT + nf * 8;
                if (c0 == r0)     c[mi][nf][0] = 0.f;
                if (c0 + 1 == r0) c[mi][nf][1] = 0.f;
                if (c0 == r1)     c[mi][nf][2] = 0.f;
                if (c0 + 1 == r1) c[mi][nf][3] = 0.f;
            }
        }
    }

    // ---- row sums -> block I -----------------------------------------------
    float* sRed = (float*)smem_g;        // [128][17]
    #pragma unroll
    for (int mi = 0; mi < 4; ++mi) {
        float s0 = 0.f, s1 = 0.f;
        #pragma unroll
        for (int nf = 0; nf < 4; ++nf) {
            s0 += c[mi][nf][0] + c[mi][nf][1];
            s1 += c[mi][nf][2] + c[mi][nf][3];
        }
        int r = warpM * 64 + mi * 16 + (lane >> 2);
        sRed[r * 17 + warpN * 4 + (lane & 3)] = s0;
        sRed[(r + 8) * 17 + warpN * 4 + (lane & 3)] = s1;
    }
    __syncthreads();
    if (tid < 128) {
        float s = 0.0f;
        #pragma unroll
        for (int j = 0; j < 16; ++j) s += sRed[tid * 17 + j];
        atomicAdd(&g_rowsum[rowBase + tid], s);
    }

    // ---- column sums -> block J (off-diagonal only) ------------------------
    if (!diag) {
        float* sCol = (float*)(smem_g + 8704);   // [2][128]
        #pragma unroll
        for (int nf = 0; nf < 4; ++nf) {
            float s0 = 0.f, s1 = 0.f;
            #pragma unroll
            for (int mi = 0; mi < 4; ++mi) {
                s0 += c[mi][nf][0] + c[mi][nf][2];
                s1 += c[mi][nf][1] + c[mi][nf][3];
            }
            #pragma unroll
            for (int o = 4; o <= 16; o <<= 1) {
                s0 += __shfl_xor_sync(0xFFFFFFFFu, s0, o);
                s1 += __shfl_xor_sync(0xFFFFFFFFu, s1, o);
            }
            if (lane < 4) {
                int col = warpN * 32 + nf * 8 + lane * 2;
                sCol[warpM * 128 + col]     = s0;
                sCol[warpM * 128 + col + 1] = s1;
            }
        }
        __syncthreads();
        if (tid < 128)
            atomicAdd(&g_rowsum[colBase + tid], sCol[tid] + sCol[128 + tid]);
    }
    __syncthreads();

    // ---- last-CTA final reduction ------------------------------------------
    volatile unsigned* flag = (volatile unsigned*)(smem_g + 12288);
    if (tid == 0) {
        __threadfence();
        unsigned v = atomicAdd(&g_ticket, 1u);
        *flag = (v == (NPAIR - 1)) ? 1u : 0u;
    }
    __syncthreads();
    if (*flag) {
        float acc = 0.0f;
        for (int i = tid; i < N_TOT; i += 256)
            acc += __logf(__ldcg(&g_rowsum[i])) - g_pos[i];
        #pragma unroll
        for (int o = 16; o; o >>= 1) acc += __shfl_xor_sync(0xFFFFFFFFu, acc, o);
        float* wsum = (float*)(smem_g + 12352);
        if (lane == 0) wsum[wid] = acc;
        __syncthreads();
        if (tid == 0) {
            float tot = 0.f;
            #pragma unroll
            for (int w = 0; w < 8; ++w) tot += wsum[w];
            out[0] = tot * (1.0f / (float)N_TOT);
            g_ticket = 0u;               // reset for graph replay
        }
    }
}

// ---------------------------------------------------------------------------
extern "C" void kernel_launch(void* const* d_in, const int* in_sizes, int n_in,
                              void* d_out, int out_size) {
    const float* zi = (const float*)d_in[0];
    const float* zj = (const float*)d_in[1];
    float* out = (float*)d_out;

    cudaFuncSetAttribute(k_gemm, cudaFuncAttributeMaxDynamicSharedMemorySize, 65536);

    k_normpos<<<BHALF / 8, 256>>>(zi, zj);
    k_gemm<<<NPAIR, 256, 65536>>>(out);
}